// round 13
// baseline (speedup 1.0000x reference)
#include <cuda_runtime.h>
#include <cfloat>

// Problem constants (reference: xyz [4, 8192, 3], K=16)
#define BB   4
#define NN   8192
#define GG   16
#define NC   (GG * GG * GG)      // 4096 cells
#define CAP  160                 // bucket capacity per cell (max obs ~90)
#define KK   16
#define TPB  128                 // 4 warps per search block
#define WPB  4
#define NCH  4                   // pair-chunk split (grid.y)
#define TILE 2048                // packed candidate tile per block
#define FULL 0xffffffffu

// ---- device scratch (static: allocation-free) ----
__device__ float4 g_pts[BB][NC * CAP];   // bucketed points (x,y,z,|x|^2)
__device__ int    g_pidx[BB][NC * CAP];  // original indices
__device__ int    g_cnt[BB][NC];         // per-cell counts
__device__ float  g_bb[BB][6];           // bbox

__device__ __forceinline__ bool lex_less(float d, int i, float ed, int ei) {
    return (d < ed) || (d == ed && i < ei);
}

// Ascending lexicographic bitonic sort of 32 (d,i) pairs across the warp.
__device__ __forceinline__ void bitonic32(float& d, int& i, int lane) {
#pragma unroll
    for (int k = 2; k <= 32; k <<= 1) {
#pragma unroll
        for (int j = k >> 1; j > 0; j >>= 1) {
            const float od = __shfl_xor_sync(FULL, d, j);
            const int   oi = __shfl_xor_sync(FULL, i, j);
            const bool keep_min = ((lane & k) == 0) == ((lane & j) == 0);
            const bool less = lex_less(od, oi, d, i);
            if (keep_min == less) { d = od; i = oi; }
        }
    }
}

// ---- 1: per-batch bbox ----
__global__ __launch_bounds__(256)
void k_bbox(const float* __restrict__ xyz) {
    const int b = blockIdx.x;
    const float* base = xyz + (size_t)b * NN * 3;
    float mn0 = FLT_MAX, mn1 = FLT_MAX, mn2 = FLT_MAX;
    float mx0 = -FLT_MAX, mx1 = -FLT_MAX, mx2 = -FLT_MAX;
    for (int i = threadIdx.x; i < NN; i += 256) {
        const float x = base[3 * i + 0], y = base[3 * i + 1], z = base[3 * i + 2];
        mn0 = fminf(mn0, x); mx0 = fmaxf(mx0, x);
        mn1 = fminf(mn1, y); mx1 = fmaxf(mx1, y);
        mn2 = fminf(mn2, z); mx2 = fmaxf(mx2, z);
    }
#pragma unroll
    for (int o = 16; o; o >>= 1) {
        mn0 = fminf(mn0, __shfl_xor_sync(FULL, mn0, o));
        mn1 = fminf(mn1, __shfl_xor_sync(FULL, mn1, o));
        mn2 = fminf(mn2, __shfl_xor_sync(FULL, mn2, o));
        mx0 = fmaxf(mx0, __shfl_xor_sync(FULL, mx0, o));
        mx1 = fmaxf(mx1, __shfl_xor_sync(FULL, mx1, o));
        mx2 = fmaxf(mx2, __shfl_xor_sync(FULL, mx2, o));
    }
    __shared__ float s[6][8];
    const int w = threadIdx.x >> 5, l = threadIdx.x & 31;
    if (l == 0) {
        s[0][w] = mn0; s[1][w] = mn1; s[2][w] = mn2;
        s[3][w] = mx0; s[4][w] = mx1; s[5][w] = mx2;
    }
    __syncthreads();
    if (threadIdx.x == 0) {
        float a0 = FLT_MAX, a1 = FLT_MAX, a2 = FLT_MAX;
        float b0 = -FLT_MAX, b1 = -FLT_MAX, b2 = -FLT_MAX;
#pragma unroll
        for (int i = 0; i < 8; i++) {
            a0 = fminf(a0, s[0][i]); a1 = fminf(a1, s[1][i]); a2 = fminf(a2, s[2][i]);
            b0 = fmaxf(b0, s[3][i]); b1 = fmaxf(b1, s[4][i]); b2 = fmaxf(b2, s[5][i]);
        }
        g_bb[b][0] = a0 - 1e-4f; g_bb[b][1] = a1 - 1e-4f; g_bb[b][2] = a2 - 1e-4f;
        g_bb[b][3] = b0 + 1e-4f; g_bb[b][4] = b1 + 1e-4f; g_bb[b][5] = b2 + 1e-4f;
    }
}

// ---- 2: zero counters ----
__global__ void k_zero() {
    const int i = blockIdx.x * blockDim.x + threadIdx.x;
    if (i < BB * NC) ((int*)g_cnt)[i] = 0;
}

// Cell assignment — SAME formula everywhere.
__device__ __forceinline__ int cell1(float v, float mn, float inv) {
    int c = (int)((v - mn) * inv);
    return min(GG - 1, max(0, c));
}

// ---- 3: build buckets ----
__global__ void k_build(const float* __restrict__ xyz) {
    const int gi = blockIdx.x * blockDim.x + threadIdx.x;
    if (gi >= BB * NN) return;
    const int b = gi >> 13, i = gi & (NN - 1);
    const float* base = xyz + (size_t)b * NN * 3;
    const float x = base[3 * i + 0], y = base[3 * i + 1], z = base[3 * i + 2];
    const float mnx = g_bb[b][0], mny = g_bb[b][1], mnz = g_bb[b][2];
    const float ivx = GG / (g_bb[b][3] - mnx);
    const float ivy = GG / (g_bb[b][4] - mny);
    const float ivz = GG / (g_bb[b][5] - mnz);
    const int cx = cell1(x, mnx, ivx), cy = cell1(y, mny, ivy), cz = cell1(z, mnz, ivz);
    const int cc = (cz * GG + cy) * GG + cx;
    const int pos = atomicAdd(&g_cnt[b][cc], 1);
    if (pos < CAP) {
        g_pts[b][cc * CAP + pos] = make_float4(x, y, z, x * x + y * y + z * z); // R1 form
        g_pidx[b][cc * CAP + pos] = i;
    }
}

// ---- 4: block-per-cell kNN with shared packed smem tile ----
__global__ __launch_bounds__(TPB)
void k_search(const float* __restrict__ xyz, float* __restrict__ out, int out_size) {
    __shared__ float4 s_pts[TILE];
    __shared__ unsigned short s_id[TILE];
    __shared__ int s_cbase[27], s_ccnt[27], s_pref[28];
    __shared__ int s_meta[2];   // [0]=ncell_fit, [1]=T_fit

    const int bc = blockIdx.x;
    const int b  = bc >> 12;                  // NC = 4096
    const int c  = bc & (NC - 1);
    const int chunk = blockIdx.y;
    const int cnt_home = min(g_cnt[b][c], CAP);
    const int np = (cnt_home + 1) >> 1;
    if (np <= chunk) return;                  // uniform exit (incl. empty cells)

    const int lane = threadIdx.x & 31;
    const int wid  = threadIdx.x >> 5;
    const int t    = lane & 15;
    const int seg  = lane >> 4;
    const int cx = c & 15, cy = (c >> 4) & 15, cz = c >> 8;

    const float mnx = g_bb[b][0], mny = g_bb[b][1], mnz = g_bb[b][2];
    const float ex = g_bb[b][3] - mnx, ey = g_bb[b][4] - mny, ez = g_bb[b][5] - mnz;
    const float wx = ex * (1.0f / GG), wy = ey * (1.0f / GG), wz = ez * (1.0f / GG);

    // 27-cell neighborhood table
    if (threadIdx.x < 27) {
        const int dz = threadIdx.x / 9 - 1;
        const int dy = (threadIdx.x / 3) % 3 - 1;
        const int dx = threadIdx.x % 3 - 1;
        const int zz = cz + dz, yy = cy + dy, xx = cx + dx;
        int cb = 0, cn = 0;
        if (zz >= 0 && zz < GG && yy >= 0 && yy < GG && xx >= 0 && xx < GG) {
            const int cc = (zz * GG + yy) * GG + xx;
            cb = cc * CAP;
            cn = min(g_cnt[b][cc], CAP);
        }
        s_cbase[threadIdx.x] = cb;
        s_ccnt[threadIdx.x]  = cn;
    }
    __syncthreads();
    if (threadIdx.x == 0) {
        int acc = 0, nf = 27;
        for (int i = 0; i < 27; i++) {
            s_pref[i] = acc;
            const int cn = s_ccnt[i];
            if (acc + cn > TILE && nf == 27) nf = i;
            acc += cn;
        }
        s_pref[27] = acc;
        s_meta[0] = nf;
        s_meta[1] = (nf == 27) ? acc : s_pref[nf];
    }
    __syncthreads();
    const int nf = s_meta[0];
    const int T  = s_meta[1];

    const float4* __restrict__ pts  = g_pts[b];
    const int*    __restrict__ pidx = g_pidx[b];

    // Packed cooperative tile load
    for (int td = threadIdx.x; td < T; td += TPB) {
        int ci2 = 0;
        while (s_pref[ci2 + 1] <= td) ci2++;
        const int src = s_cbase[ci2] + (td - s_pref[ci2]);
        s_pts[td] = pts[src];
        s_id[td]  = (unsigned short)pidx[src];
    }
    __syncthreads();

    const float* __restrict__ bx = xyz + (size_t)b * NN * 3;
    const size_t feat_total = (size_t)BB * NN * KK * 10;
    const bool write_idx = ((size_t)out_size >= feat_total + (size_t)BB * NN * KK);

    for (int pr = chunk + NCH * wid; pr < np; pr += NCH * WPB) {
        const int sl0 = 2 * pr;
        const int sl1 = min(sl0 + 1, cnt_home - 1);    // odd count: self-pair (benign)
        const float4 P0 = pts[c * CAP + sl0];
        const float4 P1 = pts[c * CAP + sl1];
        const int qid0 = pidx[c * CAP + sl0];
        const int qid1 = pidx[c * CAP + sl1];
        const float q0x = P0.x, q0y = P0.y, q0z = P0.z, sq0 = P0.w;
        const float q1x = P1.x, q1y = P1.y, q1z = P1.z, sq1 = P1.w;

        float ld = FLT_MAX;
        int   li = 0x7fffffff;
        float tau0 = FLT_MAX, tau1 = FLT_MAX;
        bool warm = false, done = false;

#define ROUND(CC, CI)                                                           \
        {                                                                       \
            float dot0 = q0x * (CC).x;                                          \
            dot0 = fmaf(q0y, (CC).y, dot0);                                     \
            dot0 = fmaf(q0z, (CC).z, dot0);                                     \
            float dot1 = q1x * (CC).x;                                          \
            dot1 = fmaf(q1y, (CC).y, dot1);                                     \
            dot1 = fmaf(q1z, (CC).z, dot1);                                     \
            const float d2a = fmaf(-2.0f, dot0, sq0 + (CC).w);                  \
            const float d2b = fmaf(-2.0f, dot1, sq1 + (CC).w);                  \
            unsigned m0 = __ballot_sync(FULL, d2a < tau0);                      \
            unsigned m1 = __ballot_sync(FULL, d2b < tau1);                      \
            if (m0 | m1) {                                                      \
                const bool had0 = (m0 != 0), had1 = (m1 != 0);                  \
                while (m0) {                                                    \
                    const int src = __ffs(m0) - 1;                              \
                    m0 &= m0 - 1;                                               \
                    const float dv = __shfl_sync(FULL, d2a, src);               \
                    const int   iv = __shfl_sync(FULL, (CI), src);              \
                    const float pd = __shfl_up_sync(FULL, ld, 1, 16);           \
                    const int   pi2 = __shfl_up_sync(FULL, li, 1, 16);          \
                    const bool ct = lex_less(dv, iv, ld, li);                   \
                    const bool cp2 = (t > 0) && lex_less(dv, iv, pd, pi2);      \
                    if (seg == 0 && ct) { ld = cp2 ? pd : dv; li = cp2 ? pi2 : iv; } \
                }                                                               \
                while (m1) {                                                    \
                    const int src = __ffs(m1) - 1;                              \
                    m1 &= m1 - 1;                                               \
                    const float dv = __shfl_sync(FULL, d2b, src);               \
                    const int   iv = __shfl_sync(FULL, (CI), src);              \
                    const float pd = __shfl_up_sync(FULL, ld, 1, 16);           \
                    const int   pi2 = __shfl_up_sync(FULL, li, 1, 16);          \
                    const bool ct = lex_less(dv, iv, ld, li);                   \
                    const bool cp2 = (t > 0) && lex_less(dv, iv, pd, pi2);      \
                    if (seg == 1 && ct) { ld = cp2 ? pd : dv; li = cp2 ? pi2 : iv; } \
                }                                                               \
                if (had0) tau0 = __shfl_sync(FULL, ld, 15);                     \
                if (had1) tau1 = __shfl_sync(FULL, ld, 31);                     \
            }                                                                   \
        }

#define WARMUP(CC, CI)                                                          \
        {                                                                       \
            float dot0 = q0x * (CC).x;                                          \
            dot0 = fmaf(q0y, (CC).y, dot0);                                     \
            dot0 = fmaf(q0z, (CC).z, dot0);                                     \
            float dot1 = q1x * (CC).x;                                          \
            dot1 = fmaf(q1y, (CC).y, dot1);                                     \
            dot1 = fmaf(q1z, (CC).z, dot1);                                     \
            const float d2a = fmaf(-2.0f, dot0, sq0 + (CC).w);                  \
            const float d2b = fmaf(-2.0f, dot1, sq1 + (CC).w);                  \
            float da = d2a; int ia = (CI);                                      \
            bitonic32(da, ia, lane);                                            \
            float db = d2b; int ib = (CI);                                      \
            bitonic32(db, ib, lane);                                            \
            const float d1v = __shfl_sync(FULL, db, (lane - 16) & 31);          \
            const int   i1v = __shfl_sync(FULL, ib, (lane - 16) & 31);          \
            ld = seg ? d1v : da;                                                \
            li = seg ? i1v : ia;                                                \
            tau0 = __shfl_sync(FULL, ld, 15);                                   \
            tau1 = __shfl_sync(FULL, ld, 31);                                   \
        }

        // ---- Ring 1: stream the packed smem tile (full 32-lane rounds) ----
        for (int p0 = 0; p0 < T; p0 += 32) {
            const int p = p0 + lane;
            const bool ok = p < T;
            const float4 cc = ok ? s_pts[p] : make_float4(0.f, 0.f, 0.f, FLT_MAX);
            const int   ci = ok ? (int)s_id[p] : 0x7fffffff;
            if (!warm) { WARMUP(cc, ci); warm = true; }
            else       { ROUND(cc, ci); }
        }
        // Leftover cells that did not fit the tile (practically never)
        for (int lc = nf; lc < 27; lc++) {
            const int cb = s_cbase[lc], cn = s_ccnt[lc];
            for (int p0 = 0; p0 < cn; p0 += 32) {
                const int p = p0 + lane;
                const bool ok = p < cn;
                const float4 cc = ok ? pts[cb + p] : make_float4(0.f, 0.f, 0.f, FLT_MAX);
                const int   ci = ok ? pidx[cb + p] : 0x7fffffff;
                if (!warm) { WARMUP(cc, ci); warm = true; }
                else       { ROUND(cc, ci); }
            }
        }

#define CHECKDONE(R)                                                            \
        {                                                                       \
            const int X0 = cx - (R), X1 = cx + (R);                             \
            const int Y0 = cy - (R), Y1 = cy + (R);                             \
            const int Z0 = cz - (R), Z1 = cz + (R);                             \
            const bool covered = X0 <= 0 && X1 >= GG - 1 && Y0 <= 0 &&          \
                                 Y1 >= GG - 1 && Z0 <= 0 && Z1 >= GG - 1;       \
            float b0d = FLT_MAX, b1d = FLT_MAX;                                 \
            if (X0 > 0) {                                                       \
                b0d = fminf(b0d, q0x - (mnx + X0 * wx));                        \
                b1d = fminf(b1d, q1x - (mnx + X0 * wx));                        \
            }                                                                   \
            if (X1 < GG - 1) {                                                  \
                b0d = fminf(b0d, (mnx + (X1 + 1) * wx) - q0x);                  \
                b1d = fminf(b1d, (mnx + (X1 + 1) * wx) - q1x);                  \
            }                                                                   \
            if (Y0 > 0) {                                                       \
                b0d = fminf(b0d, q0y - (mny + Y0 * wy));                        \
                b1d = fminf(b1d, q1y - (mny + Y0 * wy));                        \
            }                                                                   \
            if (Y1 < GG - 1) {                                                  \
                b0d = fminf(b0d, (mny + (Y1 + 1) * wy) - q0y);                  \
                b1d = fminf(b1d, (mny + (Y1 + 1) * wy) - q1y);                  \
            }                                                                   \
            if (Z0 > 0) {                                                       \
                b0d = fminf(b0d, q0z - (mnz + Z0 * wz));                        \
                b1d = fminf(b1d, q1z - (mnz + Z0 * wz));                        \
            }                                                                   \
            if (Z1 < GG - 1) {                                                  \
                b0d = fminf(b0d, (mnz + (Z1 + 1) * wz) - q0z);                  \
                b1d = fminf(b1d, (mnz + (Z1 + 1) * wz) - q1z);                  \
            }                                                                   \
            const bool d0 = (tau0 < FLT_MAX) && (tau0 <= 0.98f * b0d * b0d);    \
            const bool d1 = (tau1 < FLT_MAX) && (tau1 <= 0.98f * b1d * b1d);    \
            done = covered || (d0 && d1);                                       \
        }

        CHECKDONE(1);

        // ---- Rings r >= 2: serial shell walk from global (rare, ~12%) ----
        for (int r = 2; r <= GG && !done; r++) {
            for (int dz = -r; dz <= r; dz++) {
                const int zz = cz + dz;
                if (zz < 0 || zz >= GG) continue;
                for (int dy = -r; dy <= r; dy++) {
                    const int yy = cy + dy;
                    if (yy < 0 || yy >= GG) continue;
                    const bool face = (abs(dz) == r) || (abs(dy) == r);
                    for (int dx = -r; dx <= r; dx++) {
                        if (!face && abs(dx) != r) continue;
                        const int xx = cx + dx;
                        if (xx < 0 || xx >= GG) continue;
                        const int cc2 = (zz * GG + yy) * GG + xx;
                        const int cb = cc2 * CAP;
                        const int cn = min(g_cnt[b][cc2], CAP);
                        for (int p0 = 0; p0 < cn; p0 += 32) {
                            const int p = p0 + lane;
                            const bool ok = p < cn;
                            const float4 c2 = ok ? pts[cb + p] : make_float4(0.f, 0.f, 0.f, FLT_MAX);
                            const int   i2 = ok ? pidx[cb + p] : 0x7fffffff;
                            ROUND(c2, i2);
                        }
                    }
                }
            }
            CHECKDONE(r);
        }
#undef ROUND
#undef WARMUP
#undef CHECKDONE

        // ---- Epilogue: features [B,N,K,10] then indices [B,N,K] as float ----
        {
            const int   q  = seg ? qid1 : qid0;
            const float qx = seg ? q1x : q0x;
            const float qy = seg ? q1y : q0y;
            const float qz = seg ? q1z : q0z;
            const size_t qlin = (size_t)b * NN + q;
            const int j = li;
            const float nx = bx[3 * j + 0];
            const float ny = bx[3 * j + 1];
            const float nz = bx[3 * j + 2];

            float* p = out + qlin * KK * 10 + (size_t)t * 10;
            p[0] = ld;
            p[1] = qx - nx;
            p[2] = qy - ny;
            p[3] = qz - nz;
            p[4] = qx;
            p[5] = qy;
            p[6] = qz;
            p[7] = nx;
            p[8] = ny;
            p[9] = nz;
            if (write_idx) out[feat_total + qlin * KK + t] = (float)j;
        }
    }
}

extern "C" void kernel_launch(void* const* d_in, const int* in_sizes, int n_in,
                              void* d_out, int out_size) {
    const float* xyz = (const float*)d_in[0];
    float* out = (float*)d_out;

    k_bbox<<<BB, 256>>>(xyz);                              // launch 1
    k_zero<<<(BB * NC + 255) / 256, 256>>>();              // launch 2
    k_build<<<(BB * NN + 255) / 256, 256>>>(xyz);          // launch 3
    dim3 grid(BB * NC, NCH);
    k_search<<<grid, TPB>>>(xyz, out, out_size);           // launch 4 (profiled)
}

// round 14
// speedup vs baseline: 2.0673x; 2.0673x over previous
#include <cuda_runtime.h>
#include <cfloat>

// Problem constants (reference: xyz [4, 8192, 3], K=16)
#define BB   4
#define NN   8192
#define NB   128                 // z bins per batch
#define KK   16
#define TPB  256                 // 8 warps, 16 queries per block
#define FULL 0xffffffffu

// ---- device scratch (static: allocation-free) ----
__device__ float4 g_zpts[BB][NN];      // z-sorted points (x,y,z,|x|^2)
__device__ int    g_zidx[BB][NN];      // original indices, z-sorted
__device__ int    g_bcnt[BB][NB];      // bin counts
__device__ int    g_bst[BB][NB + 1];   // bin start offsets
__device__ int    g_bcur[BB][NB];      // scatter cursors
__device__ float  g_zmm[BB][2];        // zmin, zmax (with margin)

__device__ __forceinline__ bool lex_less(float d, int i, float ed, int ei) {
    return (d < ed) || (d == ed && i < ei);
}

// Ascending lexicographic bitonic sort of 32 (d,i) pairs across the warp.
__device__ __forceinline__ void bitonic32(float& d, int& i, int lane) {
#pragma unroll
    for (int k = 2; k <= 32; k <<= 1) {
#pragma unroll
        for (int j = k >> 1; j > 0; j >>= 1) {
            const float od = __shfl_xor_sync(FULL, d, j);
            const int   oi = __shfl_xor_sync(FULL, i, j);
            const bool keep_min = ((lane & k) == 0) == ((lane & j) == 0);
            const bool less = lex_less(od, oi, d, i);
            if (keep_min == less) { d = od; i = oi; }
        }
    }
}

// Bin assignment — SAME formula in count/scatter/search.
__device__ __forceinline__ int zbin(float z, float mn, float inv) {
    int c = (int)((z - mn) * inv);
    return min(NB - 1, max(0, c));
}

// ---- 1: per-batch z min/max ----
__global__ __launch_bounds__(256)
void k_zbox(const float* __restrict__ xyz) {
    const int b = blockIdx.x;
    const float* base = xyz + (size_t)b * NN * 3;
    float mn = FLT_MAX, mx = -FLT_MAX;
    for (int i = threadIdx.x; i < NN; i += 256) {
        const float z = base[3 * i + 2];
        mn = fminf(mn, z);
        mx = fmaxf(mx, z);
    }
#pragma unroll
    for (int o = 16; o; o >>= 1) {
        mn = fminf(mn, __shfl_xor_sync(FULL, mn, o));
        mx = fmaxf(mx, __shfl_xor_sync(FULL, mx, o));
    }
    __shared__ float s[2][8];
    const int w = threadIdx.x >> 5, l = threadIdx.x & 31;
    if (l == 0) { s[0][w] = mn; s[1][w] = mx; }
    __syncthreads();
    if (threadIdx.x == 0) {
        float a = FLT_MAX, c = -FLT_MAX;
#pragma unroll
        for (int i = 0; i < 8; i++) { a = fminf(a, s[0][i]); c = fmaxf(c, s[1][i]); }
        g_zmm[b][0] = a - 1e-4f;
        g_zmm[b][1] = c + 1e-4f;
    }
}

// ---- 2: zero bin counters ----
__global__ void k_zero() {
    const int i = blockIdx.x * blockDim.x + threadIdx.x;
    if (i < BB * NB) ((int*)g_bcnt)[i] = 0;
}

// ---- 3: count per bin ----
__global__ void k_count(const float* __restrict__ xyz) {
    const int gi = blockIdx.x * blockDim.x + threadIdx.x;
    if (gi >= BB * NN) return;
    const int b = gi >> 13, i = gi & (NN - 1);
    const float z = xyz[(size_t)b * NN * 3 + 3 * i + 2];
    const float mn = g_zmm[b][0];
    const float inv = NB / (g_zmm[b][1] - mn);
    atomicAdd(&g_bcnt[b][zbin(z, mn, inv)], 1);
}

// ---- 4: scan bins (1 block of 128 per batch) ----
__global__ __launch_bounds__(NB)
void k_scan() {
    const int b = blockIdx.x, t = threadIdx.x;
    const int lane = t & 31, w = t >> 5;
    const int c = g_bcnt[b][t];
    int s = c;
#pragma unroll
    for (int o = 1; o < 32; o <<= 1) {
        const int v = __shfl_up_sync(FULL, s, o);
        if (lane >= o) s += v;
    }
    __shared__ int ws[4], wo[4];
    if (lane == 31) ws[w] = s;
    __syncthreads();
    if (t == 0) {
        int a = 0;
#pragma unroll
        for (int i = 0; i < 4; i++) { wo[i] = a; a += ws[i]; }
    }
    __syncthreads();
    const int excl = s - c + wo[w];
    g_bst[b][t] = excl;
    g_bcur[b][t] = excl;
    if (t == NB - 1) g_bst[b][NB] = excl + c;   // == NN
}

// ---- 5: scatter into z-sorted order ----
__global__ void k_scatter(const float* __restrict__ xyz) {
    const int gi = blockIdx.x * blockDim.x + threadIdx.x;
    if (gi >= BB * NN) return;
    const int b = gi >> 13, i = gi & (NN - 1);
    const float* base = xyz + (size_t)b * NN * 3;
    const float x = base[3 * i + 0], y = base[3 * i + 1], z = base[3 * i + 2];
    const float mn = g_zmm[b][0];
    const float inv = NB / (g_zmm[b][1] - mn);
    const int pos = atomicAdd(&g_bcur[b][zbin(z, mn, inv)], 1);
    g_zpts[b][pos] = make_float4(x, y, z, x * x + y * y + z * z);   // frozen R1 form
    g_zidx[b][pos] = i;
}

// ---- 6: warp-per-2-queries outward z-walk exact kNN ----
__global__ __launch_bounds__(TPB)
void k_search(const float* __restrict__ xyz, float* __restrict__ out, int out_size) {
    const int lane = threadIdx.x & 31;
    const int wid  = threadIdx.x >> 5;
    const int b  = blockIdx.x / (NN / 16);
    const int p  = (blockIdx.x % (NN / 16)) * 16 + wid * 2;   // sorted position
    const int t   = lane & 15;
    const int seg = lane >> 4;

    const float4* __restrict__ zp = g_zpts[b];
    const int*    __restrict__ zi = g_zidx[b];
    const int*    __restrict__ bst = g_bst[b];

    const float4 P0 = zp[p];
    const float4 P1 = zp[p + 1];
    const int qid0 = zi[p], qid1 = zi[p + 1];
    const float q0x = P0.x, q0y = P0.y, q0z = P0.z, sq0 = P0.w;
    const float q1x = P1.x, q1y = P1.y, q1z = P1.z, sq1 = P1.w;

    const float zmn = g_zmm[b][0];
    const float wz = (g_zmm[b][1] - zmn) * (1.0f / NB);
    const float inv = NB / (g_zmm[b][1] - zmn);
    const int h = zbin(q0z, zmn, inv);

    float ld = FLT_MAX;
    int   li = 0x7fffffff;
    float tau0 = FLT_MAX, tau1 = FLT_MAX;
    bool warm = false;

#define ROUND(CC, CI)                                                           \
    {                                                                           \
        float dot0 = q0x * (CC).x;                                              \
        dot0 = fmaf(q0y, (CC).y, dot0);                                         \
        dot0 = fmaf(q0z, (CC).z, dot0);                                         \
        float dot1 = q1x * (CC).x;                                              \
        dot1 = fmaf(q1y, (CC).y, dot1);                                         \
        dot1 = fmaf(q1z, (CC).z, dot1);                                         \
        const float d2a = fmaf(-2.0f, dot0, sq0 + (CC).w);                      \
        const float d2b = fmaf(-2.0f, dot1, sq1 + (CC).w);                      \
        unsigned m0 = __ballot_sync(FULL, d2a < tau0);                          \
        unsigned m1 = __ballot_sync(FULL, d2b < tau1);                          \
        if (m0 | m1) {                                                          \
            const bool had0 = (m0 != 0), had1 = (m1 != 0);                      \
            while (m0) {                                                        \
                const int src = __ffs(m0) - 1;                                  \
                m0 &= m0 - 1;                                                   \
                const float dv = __shfl_sync(FULL, d2a, src);                   \
                const int   iv = __shfl_sync(FULL, (CI), src);                  \
                const float pd = __shfl_up_sync(FULL, ld, 1, 16);               \
                const int   pi2 = __shfl_up_sync(FULL, li, 1, 16);              \
                const bool ct = lex_less(dv, iv, ld, li);                       \
                const bool cp2 = (t > 0) && lex_less(dv, iv, pd, pi2);          \
                if (seg == 0 && ct) { ld = cp2 ? pd : dv; li = cp2 ? pi2 : iv; } \
            }                                                                   \
            while (m1) {                                                        \
                const int src = __ffs(m1) - 1;                                  \
                m1 &= m1 - 1;                                                   \
                const float dv = __shfl_sync(FULL, d2b, src);                   \
                const int   iv = __shfl_sync(FULL, (CI), src);                  \
                const float pd = __shfl_up_sync(FULL, ld, 1, 16);               \
                const int   pi2 = __shfl_up_sync(FULL, li, 1, 16);              \
                const bool ct = lex_less(dv, iv, ld, li);                       \
                const bool cp2 = (t > 0) && lex_less(dv, iv, pd, pi2);          \
                if (seg == 1 && ct) { ld = cp2 ? pd : dv; li = cp2 ? pi2 : iv; } \
            }                                                                   \
            if (had0) tau0 = __shfl_sync(FULL, ld, 15);                         \
            if (had1) tau1 = __shfl_sync(FULL, ld, 31);                         \
        }                                                                       \
    }

#define WARMUP(CC, CI)                                                          \
    {                                                                           \
        float dot0 = q0x * (CC).x;                                              \
        dot0 = fmaf(q0y, (CC).y, dot0);                                         \
        dot0 = fmaf(q0z, (CC).z, dot0);                                         \
        float dot1 = q1x * (CC).x;                                              \
        dot1 = fmaf(q1y, (CC).y, dot1);                                         \
        dot1 = fmaf(q1z, (CC).z, dot1);                                         \
        const float d2a = fmaf(-2.0f, dot0, sq0 + (CC).w);                      \
        const float d2b = fmaf(-2.0f, dot1, sq1 + (CC).w);                      \
        float da = d2a; int ia = (CI);                                          \
        bitonic32(da, ia, lane);                                                \
        float db = d2b; int ib = (CI);                                          \
        bitonic32(db, ib, lane);                                                \
        const float d1v = __shfl_sync(FULL, db, (lane - 16) & 31);              \
        const int   i1v = __shfl_sync(FULL, ib, (lane - 16) & 31);              \
        ld = seg ? d1v : da;                                                    \
        li = seg ? i1v : ia;                                                    \
        tau0 = __shfl_sync(FULL, ld, 15);                                       \
        tau1 = __shfl_sync(FULL, ld, 31);                                       \
    }

    // Process one contiguous point range with depth-1 prefetch.
#define DORANGE(PS, PE)                                                         \
    {                                                                           \
        int p0 = (PS);                                                          \
        if (!warm && p0 < (PE)) {                                               \
            const int pp = p0 + lane;                                           \
            const bool ok = pp < (PE);                                          \
            const float4 cw = ok ? zp[pp] : make_float4(0.f, 0.f, 0.f, FLT_MAX); \
            const int   cwi = ok ? zi[pp] : 0x7fffffff;                         \
            WARMUP(cw, cwi);                                                    \
            warm = true;                                                        \
            p0 += 32;                                                           \
        }                                                                       \
        if (p0 < (PE)) {                                                        \
            int pp = p0 + lane;                                                 \
            bool ok = pp < (PE);                                                \
            float4 cc = ok ? zp[pp] : make_float4(0.f, 0.f, 0.f, FLT_MAX);      \
            int    ci = ok ? zi[pp] : 0x7fffffff;                               \
            for (; p0 < (PE); p0 += 32) {                                       \
                float4 nc = make_float4(0.f, 0.f, 0.f, FLT_MAX);                \
                int    ni = 0x7fffffff;                                         \
                if (p0 + 32 < (PE)) {                                           \
                    const int np2 = p0 + 32 + lane;                             \
                    const bool nok = np2 < (PE);                                \
                    if (nok) { nc = zp[np2]; ni = zi[np2]; }                    \
                }                                                               \
                ROUND(cc, ci);                                                  \
                cc = nc; ci = ni;                                               \
            }                                                                   \
        }                                                                       \
    }

    int lo = h, hi = h;
    DORANGE(bst[h], bst[h + 1]);

    for (;;) {
        // Exact stop bound from visited-bin edges.
        float bd0 = FLT_MAX, bd1 = FLT_MAX;
        if (lo > 0) {
            const float e = zmn + lo * wz;
            bd0 = fminf(bd0, q0z - e);
            bd1 = fminf(bd1, q1z - e);
        }
        if (hi < NB - 1) {
            const float e = zmn + (hi + 1) * wz;
            bd0 = fminf(bd0, e - q0z);
            bd1 = fminf(bd1, e - q1z);
        }
        const bool cov = (lo == 0) && (hi == NB - 1);
        const bool d0 = (tau0 < FLT_MAX) && (bd0 > 0.0f) && (tau0 <= 0.98f * bd0 * bd0);
        const bool d1 = (tau1 < FLT_MAX) && (bd1 > 0.0f) && (tau1 <= 0.98f * bd1 * bd1);
        if (cov || (d0 && d1)) break;

        bool up;
        if (lo == 0) up = true;
        else if (hi == NB - 1) up = false;
        else {
            const float zm = 0.5f * (q0z + q1z);
            const float du = (zmn + (hi + 1) * wz) - zm;
            const float dd = zm - (zmn + lo * wz);
            up = du <= dd;          // extend the binding side
        }
        if (up) { hi++; DORANGE(bst[hi], bst[hi + 1]); }
        else    { lo--; DORANGE(bst[lo], bst[lo + 1]); }
    }
#undef ROUND
#undef WARMUP
#undef DORANGE

    // ---- Epilogue: features [B,N,K,10] then indices [B,N,K] as float ----
    const float* __restrict__ bx = xyz + (size_t)b * NN * 3;
    const size_t feat_total = (size_t)BB * NN * KK * 10;
    const bool write_idx = ((size_t)out_size >= feat_total + (size_t)BB * NN * KK);
    {
        const int   q  = seg ? qid1 : qid0;
        const float qx = seg ? q1x : q0x;
        const float qy = seg ? q1y : q0y;
        const float qz = seg ? q1z : q0z;
        const size_t qlin = (size_t)b * NN + q;
        const int j = li;
        const float nx = bx[3 * j + 0];
        const float ny = bx[3 * j + 1];
        const float nz = bx[3 * j + 2];

        float* o = out + qlin * KK * 10 + (size_t)t * 10;
        o[0] = ld;
        o[1] = qx - nx;
        o[2] = qy - ny;
        o[3] = qz - nz;
        o[4] = qx;
        o[5] = qy;
        o[6] = qz;
        o[7] = nx;
        o[8] = ny;
        o[9] = nz;
        if (write_idx) out[feat_total + qlin * KK + t] = (float)j;
    }
}

extern "C" void kernel_launch(void* const* d_in, const int* in_sizes, int n_in,
                              void* d_out, int out_size) {
    const float* xyz = (const float*)d_in[0];
    float* out = (float*)d_out;

    k_zbox<<<BB, 256>>>(xyz);
    k_zero<<<(BB * NB + 255) / 256, 256>>>();
    k_count<<<(BB * NN + 255) / 256, 256>>>(xyz);
    k_scan<<<BB, NB>>>();
    k_scatter<<<(BB * NN + 255) / 256, 256>>>(xyz);
    k_search<<<BB * (NN / 16), TPB>>>(xyz, out, out_size);
}